// round 6
// baseline (speedup 1.0000x reference)
#include <cuda_runtime.h>

#define N_NODES 50000
#define N_EDGES 600000
#define D 128
#define M_PAD 50048  // 391 * 128

// Scratch (allowed: __device__ globals, no runtime allocation).
// Pad rows [50000, 50048) of g_agg are never written -> stay BSS-zero forever.
__device__ float g_agg[(size_t)M_PAD * D];
__device__ float g_h[(size_t)M_PAD * D];
__device__ int g_is64;  // 1 if edge_index buffer is int64, 0 if int32

// ---- packed fp32x2 helpers (Blackwell FFMA2; identical rounding to FFMA) ----
__device__ __forceinline__ unsigned long long pack2(float x, float y) {
    unsigned long long r;
    asm("mov.b64 %0, {%1, %2};" : "=l"(r) : "f"(x), "f"(y));
    return r;
}
__device__ __forceinline__ float2 unpack2(unsigned long long v) {
    float2 r;
    asm("mov.b64 {%0, %1}, %2;" : "=f"(r.x), "=f"(r.y) : "l"(v));
    return r;
}
#define FMA2(d, a, b, c) \
    asm("fma.rn.f32x2 %0, %1, %2, %3;" : "=l"(d) : "l"(a), "l"(b), "l"(c))

// Detect edge_index dtype: int64 little-endian => high word of every index is 0.
__global__ void probe_kernel(const int* __restrict__ ei) {
    __shared__ int nonzero;
    if (threadIdx.x == 0) nonzero = 0;
    __syncthreads();
    for (int i = threadIdx.x; i < 4096; i += blockDim.x) {
        if (ei[2 * i + 1] != 0) nonzero = 1;
    }
    __syncthreads();
    if (threadIdx.x == 0) g_is64 = (nonzero == 0) ? 1 : 0;
}

// Zero the accumulator (pure write; the (1+eps)x term is fused into GEMM1).
__global__ void zero_kernel() {
    int i = blockIdx.x * blockDim.x + threadIdx.x;
    const int n4 = N_NODES * (D / 4);
    if (i < n4) ((float4*)g_agg)[i] = make_float4(0.f, 0.f, 0.f, 0.f);
}

// One warp per edge; one 16B red.global.add.v4.f32 per lane.
__global__ void scatter_kernel(const float4* __restrict__ x,
                               const int* __restrict__ ei) {
    long long idx = (long long)blockIdx.x * blockDim.x + threadIdx.x;
    int e = (int)(idx >> 5);
    int lane = (int)(idx & 31);
    if (e >= N_EDGES) return;
    int src, dst;
    if (g_is64) {
        src = ei[2 * e];
        dst = ei[2 * (N_EDGES + e)];
    } else {
        src = ei[e];
        dst = ei[N_EDGES + e];
    }
    if ((unsigned)src >= (unsigned)N_NODES || (unsigned)dst >= (unsigned)N_NODES)
        return;
    float4 v = x[(long long)src * 32 + lane];
    float* a = g_agg + (long long)dst * D + lane * 4;
    asm volatile("red.global.add.v4.f32 [%0], {%1, %2, %3, %4};"
                 :: "l"(a), "f"(v.x), "f"(v.y), "f"(v.z), "f"(v.w)
                 : "memory");
}

// out[m,n] = relu(sum_k Aeff[m,k] * W[k,n] + bias[n])
// Aeff = A + s*X when X != null (fused GIN input, GEMM1), else A (GEMM2).
// Block tile 128x128, BK=16, 256 threads, 8x8 per-thread tile via FFMA2.
__global__ void __launch_bounds__(256) gemm_relu_kernel(
    const float* __restrict__ A, const float* __restrict__ X,
    const float* __restrict__ eps, const float* __restrict__ W,
    const float* __restrict__ bias, float* __restrict__ out, int M_store) {
    __shared__ float As[16][128];  // As[k][m]
    __shared__ float Bs[16][132];  // Bs[k][n]

    const int t = threadIdx.x;
    const int m0 = blockIdx.x * 128;
    const int tm = (t / 16) * 8;
    const int tn = (t % 16) * 8;

    float s = 0.0f;
    if (X) s = 1.0f + __ldg(eps);

    unsigned long long acc2[8][4];  // acc2[i][jj] = {acc[i][2jj], acc[i][2jj+1]}
#pragma unroll
    for (int i = 0; i < 8; i++)
#pragma unroll
        for (int jj = 0; jj < 4; jj++) acc2[i][jj] = 0ULL;

    for (int kc = 0; kc < 128; kc += 16) {
#pragma unroll
        for (int l = 0; l < 2; l++) {
            int j = t + l * 256;       // 0..511
            int r = j >> 2;            // tile row 0..127
            int k4 = (j & 3) * 4;      // 0,4,8,12
            long long off = (long long)(m0 + r) * D + kc + k4;
            float4 v = *(const float4*)(A + off);
            if (X && (m0 + r) < N_NODES) {
                float4 xv = *(const float4*)(X + off);
                v.x += s * xv.x; v.y += s * xv.y;
                v.z += s * xv.z; v.w += s * xv.w;
            }
            As[k4 + 0][r] = v.x;
            As[k4 + 1][r] = v.y;
            As[k4 + 2][r] = v.z;
            As[k4 + 3][r] = v.w;
        }
#pragma unroll
        for (int l = 0; l < 2; l++) {
            int j = t + l * 256;
            int kk = j >> 5;           // 0..15
            int c4 = (j & 31) * 4;     // 0..124
            float4 v = *(const float4*)(W + (kc + kk) * D + c4);
            Bs[kk][c4 + 0] = v.x;
            Bs[kk][c4 + 1] = v.y;
            Bs[kk][c4 + 2] = v.z;
            Bs[kk][c4 + 3] = v.w;
        }
        __syncthreads();

#pragma unroll
        for (int k = 0; k < 16; k++) {
            float4 a0 = *(const float4*)&As[k][tm];
            float4 a1 = *(const float4*)&As[k][tm + 4];
            const unsigned long long* bp =
                (const unsigned long long*)&Bs[k][tn];
            unsigned long long b2[4];
            b2[0] = bp[0]; b2[1] = bp[1]; b2[2] = bp[2]; b2[3] = bp[3];
            float av[8] = {a0.x, a0.y, a0.z, a0.w, a1.x, a1.y, a1.z, a1.w};
#pragma unroll
            for (int i = 0; i < 8; i++) {
                unsigned long long a2 = pack2(av[i], av[i]);
#pragma unroll
                for (int jj = 0; jj < 4; jj++)
                    FMA2(acc2[i][jj], a2, b2[jj], acc2[i][jj]);
            }
        }
        __syncthreads();
    }

    float bv[8];
#pragma unroll
    for (int j = 0; j < 8; j++) bv[j] = __ldg(bias + tn + j);

#pragma unroll
    for (int i = 0; i < 8; i++) {
        int row = m0 + tm + i;
        if (row < M_store) {
            float* o = out + (long long)row * D + tn;
#pragma unroll
            for (int half = 0; half < 2; half++) {
                float2 r0 = unpack2(acc2[i][2 * half + 0]);
                float2 r1 = unpack2(acc2[i][2 * half + 1]);
                float4 v;
                v.x = fmaxf(r0.x + bv[4 * half + 0], 0.0f);
                v.y = fmaxf(r0.y + bv[4 * half + 1], 0.0f);
                v.z = fmaxf(r1.x + bv[4 * half + 2], 0.0f);
                v.w = fmaxf(r1.y + bv[4 * half + 3], 0.0f);
                *(float4*)(o + 4 * half) = v;
            }
        }
    }
}

extern "C" void kernel_launch(void* const* d_in, const int* in_sizes, int n_in,
                              void* d_out, int out_size) {
    const float* x = (const float*)d_in[0];
    const int* ei = (const int*)d_in[1];
    const float* W1 = (const float*)d_in[2];
    const float* b1 = (const float*)d_in[3];
    const float* W2 = (const float*)d_in[4];
    const float* b2 = (const float*)d_in[5];
    const float* eps = (const float*)d_in[6];
    float* out = (float*)d_out;

    static float* agg = nullptr;
    static float* h = nullptr;
    if (!agg) {
        cudaGetSymbolAddress((void**)&agg, g_agg);
        cudaGetSymbolAddress((void**)&h, g_h);
    }

    // 0) detect edge_index dtype (int32 vs int64)
    probe_kernel<<<1, 256>>>(ei);

    // 1) agg = 0 (reset each replay; (1+eps)*x folded into GEMM1)
    {
        int n4 = N_NODES * (D / 4);
        zero_kernel<<<(n4 + 255) / 256, 256>>>();
    }
    // 2) agg[dst] += x[src] for all edges
    {
        long long total = (long long)N_EDGES * 32;
        scatter_kernel<<<(int)((total + 255) / 256), 256>>>((const float4*)x, ei);
    }
    // 3) h = relu((agg + (1+eps)x) @ W1 + b1)
    gemm_relu_kernel<<<M_PAD / 128, 256>>>(agg, x, eps, W1, b1, h, M_PAD);
    // 4) out = relu(h @ W2 + b2)
    gemm_relu_kernel<<<M_PAD / 128, 256>>>(h, nullptr, eps, W2, b2, out, N_NODES);
}

// round 8
// speedup vs baseline: 1.0012x; 1.0012x over previous
#include <cuda_runtime.h>
#include <cstdint>

#define N_NODES 50000
#define N_EDGES 600000
#define D 128
#define M_PAD 50048  // 391 * 128

// Scratch (allowed: __device__ globals, no runtime allocation).
// Pad rows [50000, 50048) of g_agg are never written -> stay BSS-zero forever.
__device__ float g_agg[(size_t)M_PAD * D];
__device__ float g_h[(size_t)M_PAD * D];
__device__ int g_is64;  // 1 if edge_index buffer is int64, 0 if int32

// Detect edge_index dtype: int64 little-endian => high word of every index is 0.
__global__ void probe_kernel(const int* __restrict__ ei) {
    __shared__ int nonzero;
    if (threadIdx.x == 0) nonzero = 0;
    __syncthreads();
    for (int i = threadIdx.x; i < 4096; i += blockDim.x) {
        if (ei[2 * i + 1] != 0) nonzero = 1;
    }
    __syncthreads();
    if (threadIdx.x == 0) g_is64 = (nonzero == 0) ? 1 : 0;
}

// Zero the accumulator (pure write; (1+eps)x is fused into GEMM1's A load).
__global__ void zero_kernel() {
    int i = blockIdx.x * blockDim.x + threadIdx.x;
    const int n4 = N_NODES * (D / 4);
    if (i < n4) ((float4*)g_agg)[i] = make_float4(0.f, 0.f, 0.f, 0.f);
}

// One warp per edge; one 16B red.global.add.v4.f32 per lane.
__global__ void scatter_kernel(const float4* __restrict__ x,
                               const int* __restrict__ ei) {
    long long idx = (long long)blockIdx.x * blockDim.x + threadIdx.x;
    int e = (int)(idx >> 5);
    int lane = (int)(idx & 31);
    if (e >= N_EDGES) return;
    int src, dst;
    if (g_is64) {
        src = ei[2 * e];
        dst = ei[2 * (N_EDGES + e)];
    } else {
        src = ei[e];
        dst = ei[N_EDGES + e];
    }
    if ((unsigned)src >= (unsigned)N_NODES || (unsigned)dst >= (unsigned)N_NODES)
        return;
    float4 v = x[(long long)src * 32 + lane];
    float* a = g_agg + (long long)dst * D + lane * 4;
    asm volatile("red.global.add.v4.f32 [%0], {%1, %2, %3, %4};"
                 :: "l"(a), "f"(v.x), "f"(v.y), "f"(v.z), "f"(v.w)
                 : "memory");
}

// ---- tf32 helpers ----
__device__ __forceinline__ uint32_t f2tf32(float f) {
    uint32_t r;
    asm("cvt.rna.tf32.f32 %0, %1;" : "=r"(r) : "f"(f));
    return r;
}

#define MMA_TF32(c, a, b)                                            \
    asm("mma.sync.aligned.m16n8k8.row.col.f32.tf32.tf32.f32 "        \
        "{%0,%1,%2,%3}, {%4,%5,%6,%7}, {%8,%9}, {%0,%1,%2,%3};"      \
        : "+f"((c)[0]), "+f"((c)[1]), "+f"((c)[2]), "+f"((c)[3])     \
        : "r"((a)[0]), "r"((a)[1]), "r"((a)[2]), "r"((a)[3]),        \
          "r"((b)[0]), "r"((b)[1]))

// out[m,n] = relu(sum_k Aeff[m,k] * W[k,n] + bias[n])
// Aeff = A + s*X when X != null (GEMM1 GIN fuse), else A.
// 128x128 block tile, BK=16, 256 threads (8 warps, each 64x32 warp tile),
// tensor cores via 3xTF32 split (fp32-grade accuracy).
__global__ void __launch_bounds__(256) gemm_relu_tc(
    const float* __restrict__ A, const float* __restrict__ X,
    const float* __restrict__ eps, const float* __restrict__ W,
    const float* __restrict__ bias, float* __restrict__ out, int M_store) {
    // pad 136 (stride = 8 mod 32 banks): conflict-free fragment loads
    __shared__ uint32_t Ah[16][136], Al[16][136];
    __shared__ uint32_t Bh[16][136], Bl[16][136];

    const int t = threadIdx.x;
    const int lane = t & 31;
    const int wid = t >> 5;
    const int warp_m = wid & 1;   // 2 warp-rows x 64
    const int warp_n = wid >> 1;  // 4 warp-cols x 32
    const int m0 = blockIdx.x * 128;

    float s = 0.0f;
    if (X) s = 1.0f + __ldg(eps);

    float acc[4][4][4];
#pragma unroll
    for (int i = 0; i < 4; i++)
#pragma unroll
        for (int j = 0; j < 4; j++)
#pragma unroll
            for (int c = 0; c < 4; c++) acc[i][j][c] = 0.0f;

    const int q = lane >> 2;    // 0..7
    const int r4 = lane & 3;    // 0..3

    for (int kc = 0; kc < 128; kc += 16) {
        // A tile: 128 rows x 16 k, transposed + hi/lo split
#pragma unroll
        for (int l = 0; l < 2; l++) {
            int j = t + l * 256;       // 0..511
            int row = j >> 2;          // 0..127
            int k4 = (j & 3) * 4;      // 0,4,8,12
            long long off = (long long)(m0 + row) * D + kc + k4;
            float4 v = *(const float4*)(A + off);
            if (X && (m0 + row) < N_NODES) {
                float4 xv = *(const float4*)(X + off);
                v.x += s * xv.x; v.y += s * xv.y;
                v.z += s * xv.z; v.w += s * xv.w;
            }
            float vv[4] = {v.x, v.y, v.z, v.w};
#pragma unroll
            for (int p = 0; p < 4; p++) {
                uint32_t hi = f2tf32(vv[p]);
                float lo = vv[p] - __uint_as_float(hi);
                Ah[k4 + p][row] = hi;
                Al[k4 + p][row] = f2tf32(lo);
            }
        }
        // W tile: 16 k-rows x 128 cols, hi/lo split
#pragma unroll
        for (int l = 0; l < 2; l++) {
            int j = t + l * 256;
            int kk = j >> 5;           // 0..15
            int c4 = (j & 31) * 4;     // 0..124
            float4 v = *(const float4*)(W + (kc + kk) * D + c4);
            float vv[4] = {v.x, v.y, v.z, v.w};
#pragma unroll
            for (int p = 0; p < 4; p++) {
                uint32_t hi = f2tf32(vv[p]);
                float lo = vv[p] - __uint_as_float(hi);
                Bh[kk][c4 + p] = hi;
                Bl[kk][c4 + p] = f2tf32(lo);
            }
        }
        __syncthreads();

#pragma unroll
        for (int kk = 0; kk < 16; kk += 8) {
            int kr = kk + r4;
            // A fragments (m16n8k8 row-major layout)
            uint32_t ah[4][4], al[4][4];
#pragma unroll
            for (int i = 0; i < 4; i++) {
                int rm = warp_m * 64 + i * 16 + q;
                ah[i][0] = Ah[kr][rm];         al[i][0] = Al[kr][rm];
                ah[i][1] = Ah[kr][rm + 8];     al[i][1] = Al[kr][rm + 8];
                ah[i][2] = Ah[kr + 4][rm];     al[i][2] = Al[kr + 4][rm];
                ah[i][3] = Ah[kr + 4][rm + 8]; al[i][3] = Al[kr + 4][rm + 8];
            }
            // B fragments (col-major: b0 k=lane%4, n=lane/4; b1 k+4)
            uint32_t bh[4][2], bl[4][2];
#pragma unroll
            for (int j = 0; j < 4; j++) {
                int cn = warp_n * 32 + j * 8 + q;
                bh[j][0] = Bh[kr][cn];     bl[j][0] = Bl[kr][cn];
                bh[j][1] = Bh[kr + 4][cn]; bl[j][1] = Bl[kr + 4][cn];
            }
#pragma unroll
            for (int i = 0; i < 4; i++)
#pragma unroll
                for (int j = 0; j < 4; j++) {
                    MMA_TF32(acc[i][j], ah[i], bh[j]);
                    MMA_TF32(acc[i][j], ah[i], bl[j]);
                    MMA_TF32(acc[i][j], al[i], bh[j]);
                }
        }
        __syncthreads();
    }

    // Epilogue: bias + relu, float2 stores (c0/c1 cols adjacent; c2/c3 row+8)
#pragma unroll
    for (int j = 0; j < 4; j++) {
        int col = warp_n * 32 + j * 8 + 2 * r4;
        float bx = __ldg(bias + col);
        float by = __ldg(bias + col + 1);
#pragma unroll
        for (int i = 0; i < 4; i++) {
            int row0 = m0 + warp_m * 64 + i * 16 + q;
            int row1 = row0 + 8;
            if (row0 < M_store) {
                float2 v;
                v.x = fmaxf(acc[i][j][0] + bx, 0.0f);
                v.y = fmaxf(acc[i][j][1] + by, 0.0f);
                *(float2*)(out + (long long)row0 * D + col) = v;
            }
            if (row1 < M_store) {
                float2 v;
                v.x = fmaxf(acc[i][j][2] + bx, 0.0f);
                v.y = fmaxf(acc[i][j][3] + by, 0.0f);
                *(float2*)(out + (long long)row1 * D + col) = v;
            }
        }
    }
}

extern "C" void kernel_launch(void* const* d_in, const int* in_sizes, int n_in,
                              void* d_out, int out_size) {
    const float* x = (const float*)d_in[0];
    const int* ei = (const int*)d_in[1];
    const float* W1 = (const float*)d_in[2];
    const float* b1 = (const float*)d_in[3];
    const float* W2 = (const float*)d_in[4];
    const float* b2 = (const float*)d_in[5];
    const float* eps = (const float*)d_in[6];
    float* out = (float*)d_out;

    static float* agg = nullptr;
    static float* h = nullptr;
    if (!agg) {
        cudaGetSymbolAddress((void**)&agg, g_agg);
        cudaGetSymbolAddress((void**)&h, g_h);
    }

    // 0) detect edge_index dtype (int32 vs int64)
    probe_kernel<<<1, 256>>>(ei);

    // 1) agg = 0 (reset each replay)
    {
        int n4 = N_NODES * (D / 4);
        zero_kernel<<<(n4 + 255) / 256, 256>>>();
    }
    // 2) agg[dst] += x[src] for all edges
    {
        long long total = (long long)N_EDGES * 32;
        scatter_kernel<<<(int)((total + 255) / 256), 256>>>((const float4*)x, ei);
    }
    // 3) h = relu((agg + (1+eps)x) @ W1 + b1)
    gemm_relu_tc<<<M_PAD / 128, 256>>>(agg, x, eps, W1, b1, h, M_PAD);
    // 4) out = relu(h @ W2 + b2)
    gemm_relu_tc<<<M_PAD / 128, 256>>>(h, nullptr, eps, W2, b2, out, N_NODES);
}

// round 10
// speedup vs baseline: 1.1618x; 1.1605x over previous
#include <cuda_runtime.h>
#include <cstdint>

#define N_NODES 50000
#define N_EDGES 600000
#define D 128
#define M_PAD 50048  // 391 * 128

// Scratch: pad rows [50000,50048) of g_agg never written -> stay BSS-zero.
__device__ float g_agg[(size_t)M_PAD * D];
__device__ float g_h[(size_t)M_PAD * D];
__device__ int g_is64;

// Detect edge_index dtype: int64 LE => high word of every index is 0.
__global__ void probe_kernel(const int* __restrict__ ei) {
    __shared__ int nonzero;
    if (threadIdx.x == 0) nonzero = 0;
    __syncthreads();
    for (int i = threadIdx.x; i < 4096; i += blockDim.x)
        if (ei[2 * i + 1] != 0) nonzero = 1;
    __syncthreads();
    if (threadIdx.x == 0) g_is64 = (nonzero == 0) ? 1 : 0;
}

// g_agg = (1+eps)*x  (resets accumulator every replay; GEMMs stay pure)
__global__ void init_kernel(const float4* __restrict__ x,
                            const float* __restrict__ eps) {
    int i = blockIdx.x * blockDim.x + threadIdx.x;
    const int n4 = N_NODES * (D / 4);
    if (i < n4) {
        float s = 1.0f + __ldg(eps);
        float4 v = x[i];
        v.x *= s; v.y *= s; v.z *= s; v.w *= s;
        ((float4*)g_agg)[i] = v;
    }
}

// One warp per edge; one 16B red.global.add.v4.f32 per lane.
__global__ void scatter_kernel(const float4* __restrict__ x,
                               const int* __restrict__ ei) {
    long long idx = (long long)blockIdx.x * blockDim.x + threadIdx.x;
    int e = (int)(idx >> 5);
    int lane = (int)(idx & 31);
    if (e >= N_EDGES) return;
    int src, dst;
    if (g_is64) {
        src = ei[2 * e];
        dst = ei[2 * (N_EDGES + e)];
    } else {
        src = ei[e];
        dst = ei[N_EDGES + e];
    }
    if ((unsigned)src >= (unsigned)N_NODES || (unsigned)dst >= (unsigned)N_NODES)
        return;
    float4 v = x[(long long)src * 32 + lane];
    float* a = g_agg + (long long)dst * D + lane * 4;
    asm volatile("red.global.add.v4.f32 [%0], {%1, %2, %3, %4};"
                 :: "l"(a), "f"(v.x), "f"(v.y), "f"(v.z), "f"(v.w)
                 : "memory");
}

// ---- tf32 / mma / cp.async helpers ----
__device__ __forceinline__ uint32_t f2tf32(float f) {
    uint32_t r;
    asm("cvt.rna.tf32.f32 %0, %1;" : "=r"(r) : "f"(f));
    return r;
}
__device__ __forceinline__ void split_tf32(float f, uint32_t& hi, uint32_t& lo) {
    hi = f2tf32(f);
    lo = f2tf32(f - __uint_as_float(hi));
}

#define MMA_TF32(c, a, b)                                            \
    asm("mma.sync.aligned.m16n8k8.row.col.f32.tf32.tf32.f32 "        \
        "{%0,%1,%2,%3}, {%4,%5,%6,%7}, {%8,%9}, {%0,%1,%2,%3};"      \
        : "+f"((c)[0]), "+f"((c)[1]), "+f"((c)[2]), "+f"((c)[3])     \
        : "r"((a)[0]), "r"((a)[1]), "r"((a)[2]), "r"((a)[3]),        \
          "r"((b)[0]), "r"((b)[1]))

#define CP_ASYNC16(dst, src)                                         \
    asm volatile("cp.async.cg.shared.global [%0], [%1], 16;" ::      \
        "r"((uint32_t)__cvta_generic_to_shared(dst)), "l"(src))
#define CP_COMMIT()  asm volatile("cp.async.commit_group;" ::: "memory")
#define CP_WAIT(n)   asm volatile("cp.async.wait_group %0;" :: "n"(n) : "memory")

// out = relu(A @ W + bias), A: [M_PAD,128], W: [128,128].
// 128x128 block tile, BK=16, 256 threads (8 warps, 64x32 warp tiles).
// cp.async double-buffered raw-fp32 tiles; tf32 3-way split done in regs.
__global__ void __launch_bounds__(256, 2) gemm_relu_tc(
    const float* __restrict__ A, const float* __restrict__ W,
    const float* __restrict__ bias, float* __restrict__ out, int M_store) {
    // As stride 20: frag banks (20q + r4) % 32 all distinct.
    // Bs stride 136: frag banks (8r4 + q) % 32 all distinct.
    __shared__ float As[2][128][20];
    __shared__ float Bs[2][16][136];

    const int t = threadIdx.x;
    const int lane = t & 31;
    const int wid = t >> 5;
    const int warp_m = wid & 1;
    const int warp_n = wid >> 1;
    const int m0 = blockIdx.x * 128;
    const int q = lane >> 2;
    const int r4 = lane & 3;

    float acc[4][4][4];
#pragma unroll
    for (int i = 0; i < 4; i++)
#pragma unroll
        for (int j = 0; j < 4; j++)
#pragma unroll
            for (int c = 0; c < 4; c++) acc[i][j][c] = 0.0f;

    // ---- async tile loader: tile kc (16 k-cols) into buffer b ----
    auto load_tile = [&](int kc, int b) {
#pragma unroll
        for (int l = 0; l < 2; l++) {
            int j = t + l * 256;         // 0..511
            {   // A: 128 rows x 4 float4
                int row = j >> 2;
                int k4 = (j & 3) * 4;
                CP_ASYNC16(&As[b][row][k4],
                           A + (long long)(m0 + row) * D + kc * 16 + k4);
            }
            {   // B: 16 k-rows x 32 float4
                int kk = j >> 5;
                int c4 = (j & 31) * 4;
                CP_ASYNC16(&Bs[b][kk][c4],
                           W + (long long)(kc * 16 + kk) * D + c4);
            }
        }
    };

    load_tile(0, 0);
    CP_COMMIT();

    for (int kc = 0; kc < 8; kc++) {
        int b = kc & 1;
        if (kc < 7) {
            load_tile(kc + 1, b ^ 1);
            CP_COMMIT();
            CP_WAIT(1);   // tile kc complete, kc+1 in flight
        } else {
            CP_WAIT(0);
        }
        __syncthreads();

#pragma unroll
        for (int kk8 = 0; kk8 < 16; kk8 += 8) {
            int kr = kk8 + r4;
            uint32_t ah[4][4], al[4][4];
#pragma unroll
            for (int i = 0; i < 4; i++) {
                int rm = warp_m * 64 + i * 16 + q;
                split_tf32(As[b][rm][kr],         ah[i][0], al[i][0]);
                split_tf32(As[b][rm + 8][kr],     ah[i][1], al[i][1]);
                split_tf32(As[b][rm][kr + 4],     ah[i][2], al[i][2]);
                split_tf32(As[b][rm + 8][kr + 4], ah[i][3], al[i][3]);
            }
            uint32_t bh[4][2], bl[4][2];
#pragma unroll
            for (int j = 0; j < 4; j++) {
                int cn = warp_n * 32 + j * 8 + q;
                split_tf32(Bs[b][kr][cn],     bh[j][0], bl[j][0]);
                split_tf32(Bs[b][kr + 4][cn], bh[j][1], bl[j][1]);
            }
#pragma unroll
            for (int i = 0; i < 4; i++)
#pragma unroll
                for (int j = 0; j < 4; j++) {
                    MMA_TF32(acc[i][j], ah[i], bh[j]);
                    MMA_TF32(acc[i][j], ah[i], bl[j]);
                    MMA_TF32(acc[i][j], al[i], bh[j]);
                }
        }
        __syncthreads();   // protect buffer b before it is refilled at kc+2
    }

    // Epilogue: bias + relu, float2 stores
#pragma unroll
    for (int j = 0; j < 4; j++) {
        int col = warp_n * 32 + j * 8 + 2 * r4;
        float bx = __ldg(bias + col);
        float by = __ldg(bias + col + 1);
#pragma unroll
        for (int i = 0; i < 4; i++) {
            int row0 = m0 + warp_m * 64 + i * 16 + q;
            int row1 = row0 + 8;
            if (row0 < M_store) {
                float2 v;
                v.x = fmaxf(acc[i][j][0] + bx, 0.0f);
                v.y = fmaxf(acc[i][j][1] + by, 0.0f);
                *(float2*)(out + (long long)row0 * D + col) = v;
            }
            if (row1 < M_store) {
                float2 v;
                v.x = fmaxf(acc[i][j][2] + bx, 0.0f);
                v.y = fmaxf(acc[i][j][3] + by, 0.0f);
                *(float2*)(out + (long long)row1 * D + col) = v;
            }
        }
    }
}

extern "C" void kernel_launch(void* const* d_in, const int* in_sizes, int n_in,
                              void* d_out, int out_size) {
    const float* x = (const float*)d_in[0];
    const int* ei = (const int*)d_in[1];
    const float* W1 = (const float*)d_in[2];
    const float* b1 = (const float*)d_in[3];
    const float* W2 = (const float*)d_in[4];
    const float* b2 = (const float*)d_in[5];
    const float* eps = (const float*)d_in[6];
    float* out = (float*)d_out;

    static float* agg = nullptr;
    static float* h = nullptr;
    if (!agg) {
        cudaGetSymbolAddress((void**)&agg, g_agg);
        cudaGetSymbolAddress((void**)&h, g_h);
    }

    probe_kernel<<<1, 256>>>(ei);
    {
        int n4 = N_NODES * (D / 4);
        init_kernel<<<(n4 + 255) / 256, 256>>>((const float4*)x, eps);
    }
    {
        long long total = (long long)N_EDGES * 32;
        scatter_kernel<<<(int)((total + 255) / 256), 256>>>((const float4*)x, ei);
    }
    gemm_relu_tc<<<M_PAD / 128, 256>>>(agg, W1, b1, h, M_PAD);
    gemm_relu_tc<<<M_PAD / 128, 256>>>(h, W2, b2, out, N_NODES);
}

// round 11
// speedup vs baseline: 1.4938x; 1.2857x over previous
#include <cuda_runtime.h>
#include <cstdint>

#define N_NODES 50000
#define N_EDGES 600000
#define D 128
#define M_PAD 50048        // 391 * 128
#define SCAN_B 49          // ceil(50000/1024)

// Scratch (__device__ globals; no runtime allocation).
// g_agg pad rows [50000,50048) never written -> stay BSS-zero (deterministic).
__device__ float g_agg[(size_t)M_PAD * D];
__device__ float g_h[(size_t)M_PAD * D];
__device__ int g_is64;
__device__ int g_deg[N_NODES];
__device__ int g_psum[N_NODES];     // within-block exclusive scan
__device__ int g_off[N_NODES];      // global exclusive offsets
__device__ int g_cur[N_NODES];      // fill cursors
__device__ int g_btot[SCAN_B];      // block totals
__device__ int g_btot_ex[SCAN_B];   // exclusive-scanned block totals
__device__ int g_esrc[N_EDGES];     // CSR: src indices grouped by dst

// ---- edge decode (int32 vs int64 buffers) ----
__device__ __forceinline__ void edge_sd(const int* ei, int e, int& src, int& dst) {
    if (g_is64) {
        src = ei[2 * e];
        dst = ei[2 * (N_EDGES + e)];
    } else {
        src = ei[e];
        dst = ei[N_EDGES + e];
    }
}

// Detect edge_index dtype: int64 LE => high word of every index is 0.
__global__ void probe_kernel(const int* __restrict__ ei) {
    __shared__ int nonzero;
    if (threadIdx.x == 0) nonzero = 0;
    __syncthreads();
    for (int i = threadIdx.x; i < 4096; i += blockDim.x)
        if (ei[2 * i + 1] != 0) nonzero = 1;
    __syncthreads();
    if (threadIdx.x == 0) g_is64 = (nonzero == 0) ? 1 : 0;
}

__global__ void zero_deg_kernel() {
    int i = blockIdx.x * blockDim.x + threadIdx.x;
    if (i < N_NODES) g_deg[i] = 0;
}

__global__ void hist_kernel(const int* __restrict__ ei) {
    int e = blockIdx.x * blockDim.x + threadIdx.x;
    if (e >= N_EDGES) return;
    int src, dst;
    edge_sd(ei, e, src, dst);
    if ((unsigned)src >= (unsigned)N_NODES || (unsigned)dst >= (unsigned)N_NODES)
        return;
    atomicAdd(&g_deg[dst], 1);
}

// Per-block (1024) exclusive scan of g_deg; block totals to g_btot.
__global__ void __launch_bounds__(1024) scan_block_kernel() {
    __shared__ int s[1024];
    int t = threadIdx.x;
    int i = blockIdx.x * 1024 + t;
    int v = (i < N_NODES) ? g_deg[i] : 0;
    s[t] = v;
    __syncthreads();
    // Hillis-Steele inclusive scan
#pragma unroll
    for (int d = 1; d < 1024; d <<= 1) {
        int add = (t >= d) ? s[t - d] : 0;
        __syncthreads();
        s[t] += add;
        __syncthreads();
    }
    if (i < N_NODES) g_psum[i] = s[t] - v;   // exclusive
    if (t == 1023) g_btot[blockIdx.x] = s[t];
}

// Exclusive scan of SCAN_B block totals (single block of 64 threads).
__global__ void scan_tot_kernel() {
    __shared__ int s[64];
    int t = threadIdx.x;
    int v = (t < SCAN_B) ? g_btot[t] : 0;
    s[t] = v;
    __syncthreads();
#pragma unroll
    for (int d = 1; d < 64; d <<= 1) {
        int add = (t >= d) ? s[t - d] : 0;
        __syncthreads();
        s[t] += add;
        __syncthreads();
    }
    if (t < SCAN_B) g_btot_ex[t] = s[t] - v;
}

__global__ void finalize_off_kernel() {
    int i = blockIdx.x * blockDim.x + threadIdx.x;
    if (i < N_NODES) {
        int o = g_psum[i] + g_btot_ex[i >> 10];
        g_off[i] = o;
        g_cur[i] = o;
    }
}

__global__ void fill_kernel(const int* __restrict__ ei) {
    int e = blockIdx.x * blockDim.x + threadIdx.x;
    if (e >= N_EDGES) return;
    int src, dst;
    edge_sd(ei, e, src, dst);
    if ((unsigned)src >= (unsigned)N_NODES || (unsigned)dst >= (unsigned)N_NODES)
        return;
    int pos = atomicAdd(&g_cur[dst], 1);
    g_esrc[pos] = src;
}

// Warp per node: agg[n] = (1+eps)*x[n] + sum_{src in CSR[n]} x[src].
// Lane l owns float4 slice [4l,4l+4). Pure reads, no float atomics.
__global__ void gather_kernel(const float4* __restrict__ x,
                              const float* __restrict__ eps) {
    int gid = blockIdx.x * blockDim.x + threadIdx.x;
    int n = gid >> 5;
    int lane = gid & 31;
    if (n >= N_NODES) return;
    float s = 1.0f + __ldg(eps);
    int beg = g_off[n];
    int d = g_deg[n];
    float4 a = x[(long long)n * 32 + lane];
    a.x *= s; a.y *= s; a.z *= s; a.w *= s;
    for (int i = 0; i < d; i++) {
        int src = g_esrc[beg + i];           // broadcast load
        float4 v = x[(long long)src * 32 + lane];
        a.x += v.x; a.y += v.y; a.z += v.z; a.w += v.w;
    }
    ((float4*)g_agg)[(long long)n * 32 + lane] = a;
}

// ---- tf32 / mma / cp.async helpers ----
__device__ __forceinline__ uint32_t f2tf32(float f) {
    uint32_t r;
    asm("cvt.rna.tf32.f32 %0, %1;" : "=r"(r) : "f"(f));
    return r;
}
__device__ __forceinline__ void split_tf32(float f, uint32_t& hi, uint32_t& lo) {
    hi = f2tf32(f);
    lo = f2tf32(f - __uint_as_float(hi));
}

#define MMA_TF32(c, a, b)                                            \
    asm("mma.sync.aligned.m16n8k8.row.col.f32.tf32.tf32.f32 "        \
        "{%0,%1,%2,%3}, {%4,%5,%6,%7}, {%8,%9}, {%0,%1,%2,%3};"      \
        : "+f"((c)[0]), "+f"((c)[1]), "+f"((c)[2]), "+f"((c)[3])     \
        : "r"((a)[0]), "r"((a)[1]), "r"((a)[2]), "r"((a)[3]),        \
          "r"((b)[0]), "r"((b)[1]))

#define CP_ASYNC16(dst, src)                                         \
    asm volatile("cp.async.cg.shared.global [%0], [%1], 16;" ::      \
        "r"((uint32_t)__cvta_generic_to_shared(dst)), "l"(src))
#define CP_COMMIT()  asm volatile("cp.async.commit_group;" ::: "memory")
#define CP_WAIT(n)   asm volatile("cp.async.wait_group %0;" :: "n"(n) : "memory")

// out = relu(A @ W + bias); 128x128 tile, BK=16, 8 warps, cp.async dbl-buffer,
// tf32 3-way split in registers. (unchanged from R10)
__global__ void __launch_bounds__(256, 2) gemm_relu_tc(
    const float* __restrict__ A, const float* __restrict__ W,
    const float* __restrict__ bias, float* __restrict__ out, int M_store) {
    __shared__ float As[2][128][20];
    __shared__ float Bs[2][16][136];

    const int t = threadIdx.x;
    const int lane = t & 31;
    const int wid = t >> 5;
    const int warp_m = wid & 1;
    const int warp_n = wid >> 1;
    const int m0 = blockIdx.x * 128;
    const int q = lane >> 2;
    const int r4 = lane & 3;

    float acc[4][4][4];
#pragma unroll
    for (int i = 0; i < 4; i++)
#pragma unroll
        for (int j = 0; j < 4; j++)
#pragma unroll
            for (int c = 0; c < 4; c++) acc[i][j][c] = 0.0f;

    auto load_tile = [&](int kc, int b) {
#pragma unroll
        for (int l = 0; l < 2; l++) {
            int j = t + l * 256;
            {
                int row = j >> 2;
                int k4 = (j & 3) * 4;
                CP_ASYNC16(&As[b][row][k4],
                           A + (long long)(m0 + row) * D + kc * 16 + k4);
            }
            {
                int kk = j >> 5;
                int c4 = (j & 31) * 4;
                CP_ASYNC16(&Bs[b][kk][c4],
                           W + (long long)(kc * 16 + kk) * D + c4);
            }
        }
    };

    load_tile(0, 0);
    CP_COMMIT();

    for (int kc = 0; kc < 8; kc++) {
        int b = kc & 1;
        if (kc < 7) {
            load_tile(kc + 1, b ^ 1);
            CP_COMMIT();
            CP_WAIT(1);
        } else {
            CP_WAIT(0);
        }
        __syncthreads();

#pragma unroll
        for (int kk8 = 0; kk8 < 16; kk8 += 8) {
            int kr = kk8 + r4;
            uint32_t ah[4][4], al[4][4];
#pragma unroll
            for (int i = 0; i < 4; i++) {
                int rm = warp_m * 64 + i * 16 + q;
                split_tf32(As[b][rm][kr],         ah[i][0], al[i][0]);
                split_tf32(As[b][rm + 8][kr],     ah[i][1], al[i][1]);
                split_tf32(As[b][rm][kr + 4],     ah[i][2], al[i][2]);
                split_tf32(As[b][rm + 8][kr + 4], ah[i][3], al[i][3]);
            }
            uint32_t bh[4][2], bl[4][2];
#pragma unroll
            for (int j = 0; j < 4; j++) {
                int cn = warp_n * 32 + j * 8 + q;
                split_tf32(Bs[b][kr][cn],     bh[j][0], bl[j][0]);
                split_tf32(Bs[b][kr + 4][cn], bh[j][1], bl[j][1]);
            }
#pragma unroll
            for (int i = 0; i < 4; i++)
#pragma unroll
                for (int j = 0; j < 4; j++) {
                    MMA_TF32(acc[i][j], ah[i], bh[j]);
                    MMA_TF32(acc[i][j], ah[i], bl[j]);
                    MMA_TF32(acc[i][j], al[i], bh[j]);
                }
        }
        __syncthreads();
    }

#pragma unroll
    for (int j = 0; j < 4; j++) {
        int col = warp_n * 32 + j * 8 + 2 * r4;
        float bx = __ldg(bias + col);
        float by = __ldg(bias + col + 1);
#pragma unroll
        for (int i = 0; i < 4; i++) {
            int row0 = m0 + warp_m * 64 + i * 16 + q;
            int row1 = row0 + 8;
            if (row0 < M_store) {
                float2 v;
                v.x = fmaxf(acc[i][j][0] + bx, 0.0f);
                v.y = fmaxf(acc[i][j][1] + by, 0.0f);
                *(float2*)(out + (long long)row0 * D + col) = v;
            }
            if (row1 < M_store) {
                float2 v;
                v.x = fmaxf(acc[i][j][2] + bx, 0.0f);
                v.y = fmaxf(acc[i][j][3] + by, 0.0f);
                *(float2*)(out + (long long)row1 * D + col) = v;
            }
        }
    }
}

extern "C" void kernel_launch(void* const* d_in, const int* in_sizes, int n_in,
                              void* d_out, int out_size) {
    const float* x = (const float*)d_in[0];
    const int* ei = (const int*)d_in[1];
    const float* W1 = (const float*)d_in[2];
    const float* b1 = (const float*)d_in[3];
    const float* W2 = (const float*)d_in[4];
    const float* b2 = (const float*)d_in[5];
    const float* eps = (const float*)d_in[6];
    float* out = (float*)d_out;

    static float* agg = nullptr;
    static float* h = nullptr;
    if (!agg) {
        cudaGetSymbolAddress((void**)&agg, g_agg);
        cudaGetSymbolAddress((void**)&h, g_h);
    }

    const int EB = (N_EDGES + 255) / 256;

    probe_kernel<<<1, 256>>>(ei);
    zero_deg_kernel<<<(N_NODES + 255) / 256, 256>>>();
    hist_kernel<<<EB, 256>>>(ei);
    scan_block_kernel<<<SCAN_B, 1024>>>();
    scan_tot_kernel<<<1, 64>>>();
    finalize_off_kernel<<<(N_NODES + 255) / 256, 256>>>();
    fill_kernel<<<EB, 256>>>(ei);
    gather_kernel<<<(N_NODES * 32 + 255) / 256, 256>>>((const float4*)x, eps);

    gemm_relu_tc<<<M_PAD / 128, 256>>>(agg, W1, b1, h, M_PAD);
    gemm_relu_tc<<<M_PAD / 128, 256>>>(h, W2, b2, out, N_NODES);
}